// round 15
// baseline (speedup 1.0000x reference)
#include <cuda_runtime.h>
#include <cuda_fp16.h>
#include <cstdint>
#include <math.h>

#define NN 50000
#define NE 800000
#define H  256

// ---------------- device scratch ----------------
__device__ __align__(16) float g_ew[NE];
__device__ __align__(16) float g_deg[NN];          // deg, then dinv in-place
__device__ __align__(16) __half g_x1h[NN * H];     // x1 (fp16)
__device__ int   g_cnt[NN];
__device__ int   g_rowstart[NN + 1];
__device__ int   g_pos[NN];
__device__ __align__(16) int2 g_es[NE];            // packed {src, norm_bits}
__device__ float g_gsum[H];
__device__ float g_gmean[H];
__device__ float g_gterm[H];
// fp16 GEMM operands (single precision term — no split)
__device__ __align__(16) __half g_agg[NN * H];     // layer-2 aggregate
__device__ __align__(16) __half g_x2[NN * H];      // x2
__device__ __align__(16) __half g_c2[H * H];       // conv2_w
__device__ __align__(16) __half g_wa[H * H];       // actor_w1 rows 0..255

// ---------------- prep: init state + fp16 weights ----------
__global__ void k_prep(float* __restrict__ out, const float* __restrict__ b2a,
                       const float* __restrict__ cw, const float* __restrict__ aw, int N) {
    int i = blockIdx.x * blockDim.x + threadIdx.x;   // 65536 threads
    g_c2[i] = __float2half_rn(cw[i]);
    g_wa[i] = __float2half_rn(aw[i]);
    if (i < N) { g_deg[i] = 1.0f; g_cnt[i] = 0; out[i] = b2a[0]; }
    if (i < H) g_gsum[i] = 0.0f;
}

// ---------------- edge MLP + degree/count ----------------
__global__ void k_edge(const int* __restrict__ eid, const int* __restrict__ epos,
                       const float* __restrict__ id_emb, const float* __restrict__ pos_emb,
                       const float* __restrict__ W1, const float* __restrict__ b1,
                       const float* __restrict__ W2, const float* __restrict__ b2,
                       const int* __restrict__ dst, int E) {
    __shared__ float sW1[100], sb1[10], sW2[10], sb2, spe[6];
    int t = threadIdx.x;
    if (t < 100) sW1[t] = W1[t];
    if (t < 10) { sb1[t] = b1[t]; sW2[t] = W2[t]; }
    if (t == 0) sb2 = b2[0];
    if (t < 6) spe[t] = pos_emb[t];
    __syncthreads();
    int e = blockIdx.x * blockDim.x + t;
    if (e >= E) return;
    int id = eid[e], p = epos[e];
    float4 fa = *(const float4*)&id_emb[id * 8];
    float4 fb = *(const float4*)&id_emb[id * 8 + 4];
    float f[10] = {fa.x, fa.y, fa.z, fa.w, fb.x, fb.y, fb.z, fb.w,
                   spe[p * 2 + 0], spe[p * 2 + 1]};
    float acc2 = sb2;
#pragma unroll
    for (int j = 0; j < 10; j++) {
        float h = sb1[j];
#pragma unroll
        for (int i = 0; i < 10; i++) h = fmaf(f[i], sW1[i * 10 + j], h);
        h = fmaxf(h, 0.0f);
        acc2 = fmaf(h, sW2[j], acc2);
    }
    float w = 1.0f / (1.0f + __expf(-acc2));
    g_ew[e] = w;
    int d = dst[e];
    atomicAdd(&g_deg[d], w);
    atomicAdd(&g_cnt[d], 1);
}

// ---------------- parallel scan of counts -> rowstart/pos (scan ONLY) --------
__global__ void k_scan(int N, int E) {
    __shared__ int wsum[32], wbase[32];
    int t = threadIdx.x;                         // 1024
    int lane = t & 31, wid = t >> 5;
    const int CH = (NN + 1023) / 1024;
    int base = t * CH;
    int s = 0;
    for (int i = 0; i < CH; i++) { int idx = base + i; if (idx < N) s += g_cnt[idx]; }
    int inc = s;
#pragma unroll
    for (int o = 1; o < 32; o <<= 1) {
        int v = __shfl_up_sync(0xffffffff, inc, o);
        if (lane >= o) inc += v;
    }
    if (lane == 31) wsum[wid] = inc;
    __syncthreads();
    if (wid == 0) {
        int v = wsum[lane];
        int wi = v;
#pragma unroll
        for (int o = 1; o < 32; o <<= 1) {
            int u = __shfl_up_sync(0xffffffff, wi, o);
            if (lane >= o) wi += u;
        }
        wbase[lane] = wi - v;
    }
    __syncthreads();
    int run = wbase[wid] + inc - s;
    for (int i = 0; i < CH; i++) {
        int idx = base + i;
        if (idx < N) { g_rowstart[idx] = run; g_pos[idx] = run; run += g_cnt[idx]; }
    }
    if (t == 0) g_rowstart[N] = E;
}

// dinv as a wide, parallel kernel (NOT fused into the single-block scan)
__global__ void k_dinv(int N) {
    int n = blockIdx.x * blockDim.x + threadIdx.x;
    if (n < N) g_deg[n] = rsqrtf(g_deg[n]);
}

// ---------------- scatter: reorder packed (src, norm) by dst ----------------
__global__ void k_scatter(const int* __restrict__ src, const int* __restrict__ dst, int E) {
    int e = blockIdx.x * blockDim.x + threadIdx.x;
    if (e >= E) return;
    int d = dst[e];
    int s = src[e];
    float nrm = g_ew[e] * g_deg[s] * g_deg[d];
    int p = atomicAdd(&g_pos[d], 1);
    g_es[p] = make_int2(s, __float_as_int(nrm));
}

// ---------------- fused: layer-1 CSR agg + x1 GEMV (fp16 out) ----------
__global__ __launch_bounds__(256) void k_agg0x1(const float* __restrict__ x0,
                                                const float* __restrict__ W,
                                                const float* __restrict__ b, int N) {
    int t = threadIdx.x;
    int wid = t >> 5, lane = t & 31;
    int row = blockIdx.x * 8 + wid;
    if (row >= N) return;
    float dv = g_deg[row];
    int beg = g_rowstart[row], end = g_rowstart[row + 1];
    float a0 = 0.f, a1 = 0.f, a2 = 0.f;
    for (int k = beg + lane; k < end; k += 32) {
        int2 es = g_es[k];
        int s = es.x;
        float nrm = __int_as_float(es.y);
        a0 = fmaf(nrm, x0[s * 3 + 0], a0);
        a1 = fmaf(nrm, x0[s * 3 + 1], a1);
        a2 = fmaf(nrm, x0[s * 3 + 2], a2);
    }
#pragma unroll
    for (int o = 16; o > 0; o >>= 1) {
        a0 += __shfl_xor_sync(0xffffffff, a0, o);
        a1 += __shfl_xor_sync(0xffffffff, a1, o);
        a2 += __shfl_xor_sync(0xffffffff, a2, o);
    }
    float d2 = dv * dv;
    a0 = fmaf(d2, x0[row * 3 + 0], a0);
    a1 = fmaf(d2, x0[row * 3 + 1], a1);
    a2 = fmaf(d2, x0[row * 3 + 2], a2);
    __half hv[8];
#pragma unroll
    for (int i = 0; i < 8; i++) {
        int c = lane * 8 + i;
        float v = __ldg(&b[c]);
        v = fmaf(a0, __ldg(&W[c]), v);
        v = fmaf(a1, __ldg(&W[256 + c]), v);
        v = fmaf(a2, __ldg(&W[512 + c]), v);
        hv[i] = __float2half_rn(fmaxf(v, 0.0f));
    }
    *(uint4*)&g_x1h[(size_t)row * H + lane * 8] = *(uint4*)hv;
}

// ---------------- layer-2 CSR aggregation: warp per row, fp16 gather/store -----
__device__ __forceinline__ void h8_to_f(const uint4& v, float f[8]) {
    float2 p;
    p = __half22float2(*(const __half2*)&v.x); f[0] = p.x; f[1] = p.y;
    p = __half22float2(*(const __half2*)&v.y); f[2] = p.x; f[3] = p.y;
    p = __half22float2(*(const __half2*)&v.z); f[4] = p.x; f[5] = p.y;
    p = __half22float2(*(const __half2*)&v.w); f[6] = p.x; f[7] = p.y;
}

__global__ __launch_bounds__(256) void k_aggcsr(int N) {
    int wid = threadIdx.x >> 5, lane = threadIdx.x & 31;
    int row = blockIdx.x * 8 + wid;
    if (row >= N) return;
    float dv = g_deg[row];
    float d2 = dv * dv;
    float a[8];
    {
        uint4 v = *(const uint4*)&g_x1h[(size_t)row * H + lane * 8];
        float f[8]; h8_to_f(v, f);
#pragma unroll
        for (int i = 0; i < 8; i++) a[i] = d2 * f[i];
    }
    int beg = g_rowstart[row], end = g_rowstart[row + 1];
#pragma unroll 2
    for (int k = beg; k < end; k++) {
        int2 es = g_es[k];
        float nr = __int_as_float(es.y);
        uint4 v = *(const uint4*)&g_x1h[(size_t)es.x * H + lane * 8];
        float f[8]; h8_to_f(v, f);
#pragma unroll
        for (int i = 0; i < 8; i++) a[i] = fmaf(nr, f[i], a[i]);
    }
    __half hv[8];
#pragma unroll
    for (int i = 0; i < 8; i++) hv[i] = __float2half_rn(a[i]);
    *(uint4*)&g_agg[(size_t)row * H + lane * 8] = *(uint4*)hv;
}

// ---------------- mma.sync fp16 GEMM: 128x128 tile, 3-stage pipeline ----------
#define A_OFF 0
#define B_OFF 10240
#define BUF_SZ 18944
#define GEMM_SMEM (3 * BUF_SZ)
#define A_STRIDE 80    // 32 fp16 k-elems (64B) + pad (rows: 128)
#define B_STRIDE 272   // 128 fp16 n-elems (256B) + pad (rows: 32 k)

__device__ __forceinline__ uint32_t smem_u32(const void* p) {
    uint32_t a;
    asm("{ .reg .u64 t; cvta.to.shared.u64 t, %1; cvt.u32.u64 %0, t; }" : "=r"(a) : "l"(p));
    return a;
}
__device__ __forceinline__ void cp16(uint32_t dst, const void* src, int sz) {
    asm volatile("cp.async.cg.shared.global [%0], [%1], 16, %2;" :: "r"(dst), "l"(src), "r"(sz) : "memory");
}
__device__ __forceinline__ void ldsm_x4(uint32_t a[4], uint32_t addr) {
    asm volatile("ldmatrix.sync.aligned.m8n8.x4.shared.b16 {%0,%1,%2,%3}, [%4];"
                 : "=r"(a[0]), "=r"(a[1]), "=r"(a[2]), "=r"(a[3]) : "r"(addr));
}
__device__ __forceinline__ void ldsm_x4t(uint32_t a[4], uint32_t addr) {
    asm volatile("ldmatrix.sync.aligned.m8n8.x4.trans.shared.b16 {%0,%1,%2,%3}, [%4];"
                 : "=r"(a[0]), "=r"(a[1]), "=r"(a[2]), "=r"(a[3]) : "r"(addr));
}
__device__ __forceinline__ void mma_f16(float c[4], const uint32_t a[4], const uint32_t b[2]) {
    asm volatile("mma.sync.aligned.m16n8k16.row.col.f32.f16.f16.f32 "
                 "{%0,%1,%2,%3}, {%4,%5,%6,%7}, {%8,%9}, {%0,%1,%2,%3};"
                 : "+f"(c[0]), "+f"(c[1]), "+f"(c[2]), "+f"(c[3])
                 : "r"(a[0]), "r"(a[1]), "r"(a[2]), "r"(a[3]), "r"(b[0]), "r"(b[1]));
}

__device__ __forceinline__ void prefetch_chunk(
    const __half* __restrict__ A, const __half* __restrict__ B,
    int row0, int col0, int M, int kbase, int tid, uint32_t sbuf) {
#pragma unroll
    for (int l = 0; l < 2; l++) {             // A: 128 rows x 4 vec = 512 vectors
        int idx = tid + l * 256;
        int row = idx >> 2, c4 = idx & 3;
        int gr = row0 + row;
        int sz = (gr < M) ? 16 : 0;
        int grc = (gr < M) ? gr : (M - 1);
        cp16(sbuf + A_OFF + row * A_STRIDE + c4 * 16,
             A + (size_t)grc * H + kbase + c4 * 8, sz);
    }
#pragma unroll
    for (int l = 0; l < 2; l++) {             // B: 32 k x 16 vec = 512 vectors
        int idx = tid + l * 256;
        int kr = idx >> 4, cc = idx & 15;
        cp16(sbuf + B_OFF + kr * B_STRIDE + cc * 16,
             B + (size_t)(kbase + kr) * H + col0 + cc * 8, 16);
    }
    asm volatile("cp.async.commit_group;" ::: "memory");
}

template <int MODE>
__global__ __launch_bounds__(256) void k_mma(const float* __restrict__ bias,
                                             const float* __restrict__ w2,
                                             float* __restrict__ out, int M) {
    extern __shared__ char smem[];
    uint32_t sb = smem_u32(smem);
    int tid = threadIdx.x;
    int lane = tid & 31;
    int wid = tid >> 5;
    int wm = wid & 3, wn = wid >> 2;          // 4 row-groups x 2 col-groups(64)
    int row0 = blockIdx.x * 128;
    int col0 = blockIdx.y * 128;
    const __half* A = (MODE == 0) ? g_agg : g_x2;
    const __half* B = (MODE == 0) ? g_c2 : g_wa;

    float c[2][8][4];
#pragma unroll
    for (int i = 0; i < 2; i++)
#pragma unroll
        for (int j = 0; j < 8; j++)
#pragma unroll
            for (int q = 0; q < 4; q++) c[i][j][q] = 0.f;

    // 3-stage prologue: chunks 0 and 1 in flight
    prefetch_chunk(A, B, row0, col0, M, 0,  tid, sb + 0 * BUF_SZ);
    prefetch_chunk(A, B, row0, col0, M, 32, tid, sb + 1 * BUF_SZ);

    for (int ch = 0; ch < 8; ch++) {
        uint32_t buf = sb + (ch % 3) * BUF_SZ;
        if (ch < 7) asm volatile("cp.async.wait_group 1;" ::: "memory");
        else        asm volatile("cp.async.wait_group 0;" ::: "memory");
        __syncthreads();
        if (ch < 6)
            prefetch_chunk(A, B, row0, col0, M, (ch + 2) * 32, tid, sb + ((ch + 2) % 3) * BUF_SZ);
#pragma unroll
        for (int s = 0; s < 2; s++) {
            uint32_t ah[2][4];
#pragma unroll
            for (int mi = 0; mi < 2; mi++) {
                int r = wm * 32 + mi * 16 + (lane & 15);
                int kb = (s * 16 + (lane >> 4) * 8) * 2;
                ldsm_x4(ah[mi], buf + A_OFF + r * A_STRIDE + kb);
            }
            uint32_t bh[8][2];
#pragma unroll
            for (int ng = 0; ng < 4; ng++) {
                int kr = s * 16 + (lane & 7) + ((lane >> 3) & 1) * 8;
                int nc = wn * 64 + ng * 16 + (lane >> 4) * 8;
                uint32_t t4[4];
                ldsm_x4t(t4, buf + B_OFF + kr * B_STRIDE + nc * 2);
                bh[2 * ng][0] = t4[0]; bh[2 * ng][1] = t4[1];
                bh[2 * ng + 1][0] = t4[2]; bh[2 * ng + 1][1] = t4[3];
            }
#pragma unroll
            for (int mi = 0; mi < 2; mi++)
#pragma unroll
                for (int ni = 0; ni < 8; ni++)
                    mma_f16(c[mi][ni], ah[mi], bh[ni]);
        }
        __syncthreads();
    }

    if (MODE == 0) {
        float* sg = (float*)smem;            // smem free after mainloop
        if (tid < 128) sg[tid] = 0.f;
        __syncthreads();
        float bv[16];
#pragma unroll
        for (int ni = 0; ni < 8; ni++) {
            int col = col0 + wn * 64 + ni * 8 + (lane & 3) * 2;
            bv[ni * 2 + 0] = bias[col];
            bv[ni * 2 + 1] = bias[col + 1];
        }
        float cp[16];
#pragma unroll
        for (int j = 0; j < 16; j++) cp[j] = 0.f;
#pragma unroll
        for (int mi = 0; mi < 2; mi++)
#pragma unroll
            for (int hh = 0; hh < 2; hh++) {
                int row = row0 + wm * 32 + mi * 16 + (lane >> 2) + hh * 8;
                if (row >= M) continue;
#pragma unroll
                for (int ni = 0; ni < 8; ni++) {
                    int col = col0 + wn * 64 + ni * 8 + (lane & 3) * 2;
                    float v0 = fmaxf(c[mi][ni][hh * 2 + 0] + bv[ni * 2 + 0], 0.f);
                    float v1 = fmaxf(c[mi][ni][hh * 2 + 1] + bv[ni * 2 + 1], 0.f);
                    cp[ni * 2 + 0] += v0;
                    cp[ni * 2 + 1] += v1;
                    *(__half2*)&g_x2[(size_t)row * H + col] = __floats2half2_rn(v0, v1);
                }
            }
#pragma unroll
        for (int j = 0; j < 16; j++)
#pragma unroll
            for (int o = 4; o < 32; o <<= 1)
                cp[j] += __shfl_xor_sync(0xffffffff, cp[j], o);
        if ((lane >> 2) == 0) {
#pragma unroll
            for (int ni = 0; ni < 8; ni++) {
                atomicAdd(&sg[wn * 64 + ni * 8 + (lane & 3) * 2 + 0], cp[ni * 2 + 0]);
                atomicAdd(&sg[wn * 64 + ni * 8 + (lane & 3) * 2 + 1], cp[ni * 2 + 1]);
            }
        }
        __syncthreads();
        if (tid < 128) atomicAdd(&g_gsum[col0 + tid], sg[tid]);
    } else {
        float gt[16], wv[16];
#pragma unroll
        for (int ni = 0; ni < 8; ni++) {
            int col = col0 + wn * 64 + ni * 8 + (lane & 3) * 2;
            gt[ni * 2 + 0] = g_gterm[col];
            gt[ni * 2 + 1] = g_gterm[col + 1];
            wv[ni * 2 + 0] = w2[col];
            wv[ni * 2 + 1] = w2[col + 1];
        }
#pragma unroll
        for (int mi = 0; mi < 2; mi++)
#pragma unroll
            for (int hh = 0; hh < 2; hh++) {
                float s = 0.f;
#pragma unroll
                for (int ni = 0; ni < 8; ni++) {
                    float v0 = fmaxf(c[mi][ni][hh * 2 + 0] + gt[ni * 2 + 0], 0.f);
                    float v1 = fmaxf(c[mi][ni][hh * 2 + 1] + gt[ni * 2 + 1], 0.f);
                    s = fmaf(v0, wv[ni * 2 + 0], s);
                    s = fmaf(v1, wv[ni * 2 + 1], s);
                }
                s += __shfl_xor_sync(0xffffffff, s, 1);
                s += __shfl_xor_sync(0xffffffff, s, 2);
                int row = row0 + wm * 32 + mi * 16 + (lane >> 2) + hh * 8;
                if ((lane & 3) == 0 && row < M) atomicAdd(&out[row], s);
            }
    }
}

// ---------------- tail kernels ----------------
__global__ void k_gterm(const float* __restrict__ Wa, const float* __restrict__ ba, int N) {
    __shared__ float sgm[H];
    int j = threadIdx.x;
    float gm = g_gsum[j] * (1.0f / (float)N);
    sgm[j] = gm;
    g_gmean[j] = gm;
    __syncthreads();
    float acc = ba[j];
    for (int k = 0; k < H; k++) acc = fmaf(sgm[k], Wa[(H + k) * H + j], acc);
    g_gterm[j] = acc;
}

__global__ void k_critic(const float* __restrict__ W1, const float* __restrict__ b1,
                         const float* __restrict__ W2, const float* __restrict__ b2,
                         const float* __restrict__ w3, const float* __restrict__ b3,
                         float* __restrict__ out, int N) {
    __shared__ float sp[H];
    __shared__ float sc1[2 * H];
    __shared__ float sc2[H];
    int t = threadIdx.x;  // 512
    if (t < H) sp[t] = g_gmean[t];
    __syncthreads();
    float acc = b1[t];
    for (int k = 0; k < 2 * H; k++) acc = fmaf(sp[k & (H - 1)], W1[k * (2 * H) + t], acc);
    sc1[t] = fmaxf(acc, 0.0f);
    __syncthreads();
    if (t < H) {
        float a2 = b2[t];
        for (int k = 0; k < 2 * H; k++) a2 = fmaf(sc1[k], W2[k * H + t], a2);
        sc2[t] = fmaxf(a2, 0.0f);
    }
    __syncthreads();
    if (t < H) sp[t] = sc2[t] * w3[t];
    __syncthreads();
    for (int s = H / 2; s > 0; s >>= 1) {
        if (t < s) sp[t] += sp[t + s];
        __syncthreads();
    }
    if (t == 0) out[N] = sp[0] + b3[0];
}

// ---------------- launch ----------------
extern "C" void kernel_launch(void* const* d_in, const int* in_sizes, int n_in,
                              void* d_out, int out_size) {
    const float* x0       = (const float*)d_in[0];
    const int*   eidx     = (const int*)  d_in[1];
    const int*   eids     = (const int*)  d_in[2];
    const int*   epos     = (const int*)  d_in[3];
    const float* id_emb   = (const float*)d_in[4];
    const float* pos_emb  = (const float*)d_in[5];
    const float* ew_w1    = (const float*)d_in[6];
    const float* ew_b1    = (const float*)d_in[7];
    const float* ew_w2    = (const float*)d_in[8];
    const float* ew_b2    = (const float*)d_in[9];
    const float* conv1_w  = (const float*)d_in[10];
    const float* conv1_b  = (const float*)d_in[11];
    const float* conv2_w  = (const float*)d_in[12];
    const float* conv2_b  = (const float*)d_in[13];
    const float* actor_w1 = (const float*)d_in[14];
    const float* actor_b1 = (const float*)d_in[15];
    const float* actor_w2 = (const float*)d_in[16];
    const float* actor_b2 = (const float*)d_in[17];
    const float* critic_w1= (const float*)d_in[18];
    const float* critic_b1= (const float*)d_in[19];
    const float* critic_w2= (const float*)d_in[20];
    const float* critic_b2= (const float*)d_in[21];
    const float* critic_w3= (const float*)d_in[22];
    const float* critic_b3= (const float*)d_in[23];
    float* out = (float*)d_out;

    int N = in_sizes[0] / 3;
    int E = in_sizes[2];
    const int* src = eidx;
    const int* dst = eidx + E;

    cudaFuncSetAttribute(k_mma<0>, cudaFuncAttributeMaxDynamicSharedMemorySize, GEMM_SMEM);
    cudaFuncSetAttribute(k_mma<1>, cudaFuncAttributeMaxDynamicSharedMemorySize, GEMM_SMEM);

    k_prep<<<256, 256>>>(out, actor_b2, conv2_w, actor_w1, N);
    k_edge<<<(E + 255) / 256, 256>>>(eids, epos, id_emb, pos_emb,
                                     ew_w1, ew_b1, ew_w2, ew_b2, dst, E);
    k_scan<<<1, 1024>>>(N, E);
    k_dinv<<<(N + 255) / 256, 256>>>(N);
    k_scatter<<<(E + 255) / 256, 256>>>(src, dst, E);
    k_agg0x1<<<(N + 7) / 8, 256>>>(x0, conv1_w, conv1_b, N);
    k_aggcsr<<<(N + 7) / 8, 256>>>(N);

    dim3 gg((N + 127) / 128, 2);
    k_mma<0><<<gg, 256, GEMM_SMEM>>>(conv2_b, nullptr, nullptr, N);
    k_gterm<<<1, H>>>(actor_w1, actor_b1, N);
    k_mma<1><<<gg, 256, GEMM_SMEM>>>(nullptr, actor_w2, out, N);
    k_critic<<<1, 2 * H>>>(critic_w1, critic_b1, critic_w2, critic_b2,
                           critic_w3, critic_b3, out, N);
}

// round 16
// speedup vs baseline: 1.0185x; 1.0185x over previous
#include <cuda_runtime.h>
#include <cuda_fp16.h>
#include <cstdint>
#include <math.h>

#define NN 50000
#define NE 800000
#define H  256

// ---------------- device scratch ----------------
__device__ __align__(16) float g_ew[NE];
__device__ __align__(16) float g_deg[NN];          // degree (never overwritten; rsqrt inline)
__device__ __align__(16) __half g_x1h[NN * H];     // x1 (fp16)
__device__ int   g_cnt[NN];
__device__ int   g_rowstart[NN + 1];
__device__ int   g_pos[NN];
__device__ __align__(16) int2 g_es[NE];            // packed {src, norm_bits}
__device__ float g_gsum[H];
__device__ float g_gterm[H];
// fp16 GEMM operands (single precision term — no split)
__device__ __align__(16) __half g_agg[NN * H];     // layer-2 aggregate
__device__ __align__(16) __half g_x2[NN * H];      // x2
__device__ __align__(16) __half g_c2[H * H];       // conv2_w
__device__ __align__(16) __half g_wa[H * H];       // actor_w1 rows 0..255

// ---------------- prep: init state + fp16 weights ----------
__global__ void k_prep(float* __restrict__ out, const float* __restrict__ b2a,
                       const float* __restrict__ cw, const float* __restrict__ aw, int N) {
    int i = blockIdx.x * blockDim.x + threadIdx.x;   // 65536 threads
    g_c2[i] = __float2half_rn(cw[i]);
    g_wa[i] = __float2half_rn(aw[i]);
    if (i < N) { g_deg[i] = 1.0f; g_cnt[i] = 0; out[i] = b2a[0]; }
    if (i < H) g_gsum[i] = 0.0f;
}

// ---------------- edge MLP + degree/count ----------------
__global__ void k_edge(const int* __restrict__ eid, const int* __restrict__ epos,
                       const float* __restrict__ id_emb, const float* __restrict__ pos_emb,
                       const float* __restrict__ W1, const float* __restrict__ b1,
                       const float* __restrict__ W2, const float* __restrict__ b2,
                       const int* __restrict__ dst, int E) {
    __shared__ float sW1[100], sb1[10], sW2[10], sb2, spe[6];
    int t = threadIdx.x;
    if (t < 100) sW1[t] = W1[t];
    if (t < 10) { sb1[t] = b1[t]; sW2[t] = W2[t]; }
    if (t == 0) sb2 = b2[0];
    if (t < 6) spe[t] = pos_emb[t];
    __syncthreads();
    int e = blockIdx.x * blockDim.x + t;
    if (e >= E) return;
    int id = eid[e], p = epos[e];
    float4 fa = *(const float4*)&id_emb[id * 8];
    float4 fb = *(const float4*)&id_emb[id * 8 + 4];
    float f[10] = {fa.x, fa.y, fa.z, fa.w, fb.x, fb.y, fb.z, fb.w,
                   spe[p * 2 + 0], spe[p * 2 + 1]};
    float acc2 = sb2;
#pragma unroll
    for (int j = 0; j < 10; j++) {
        float h = sb1[j];
#pragma unroll
        for (int i = 0; i < 10; i++) h = fmaf(f[i], sW1[i * 10 + j], h);
        h = fmaxf(h, 0.0f);
        acc2 = fmaf(h, sW2[j], acc2);
    }
    float w = 1.0f / (1.0f + __expf(-acc2));
    g_ew[e] = w;
    int d = dst[e];
    atomicAdd(&g_deg[d], w);
    atomicAdd(&g_cnt[d], 1);
}

// ---------------- parallel scan of counts -> rowstart/pos (scan ONLY) --------
__global__ void k_scan(int N, int E) {
    __shared__ int wsum[32], wbase[32];
    int t = threadIdx.x;                         // 1024
    int lane = t & 31, wid = t >> 5;
    const int CH = (NN + 1023) / 1024;
    int base = t * CH;
    int s = 0;
    for (int i = 0; i < CH; i++) { int idx = base + i; if (idx < N) s += g_cnt[idx]; }
    int inc = s;
#pragma unroll
    for (int o = 1; o < 32; o <<= 1) {
        int v = __shfl_up_sync(0xffffffff, inc, o);
        if (lane >= o) inc += v;
    }
    if (lane == 31) wsum[wid] = inc;
    __syncthreads();
    if (wid == 0) {
        int v = wsum[lane];
        int wi = v;
#pragma unroll
        for (int o = 1; o < 32; o <<= 1) {
            int u = __shfl_up_sync(0xffffffff, wi, o);
            if (lane >= o) wi += u;
        }
        wbase[lane] = wi - v;
    }
    __syncthreads();
    int run = wbase[wid] + inc - s;
    for (int i = 0; i < CH; i++) {
        int idx = base + i;
        if (idx < N) { g_rowstart[idx] = run; g_pos[idx] = run; run += g_cnt[idx]; }
    }
    if (t == 0) g_rowstart[N] = E;
}

// ---------------- scatter: reorder packed (src, norm) by dst ----------------
// rsqrt computed inline (deterministic -> identical bits to a separate dinv pass)
__global__ void k_scatter(const int* __restrict__ src, const int* __restrict__ dst, int E) {
    int e = blockIdx.x * blockDim.x + threadIdx.x;
    if (e >= E) return;
    int d = dst[e];
    int s = src[e];
    float nrm = g_ew[e] * rsqrtf(g_deg[s]) * rsqrtf(g_deg[d]);
    int p = atomicAdd(&g_pos[d], 1);
    g_es[p] = make_int2(s, __float_as_int(nrm));
}

// ---------------- fused: layer-1 CSR agg + x1 GEMV (fp16 out) ----------
__global__ __launch_bounds__(256) void k_agg0x1(const float* __restrict__ x0,
                                                const float* __restrict__ W,
                                                const float* __restrict__ b, int N) {
    int t = threadIdx.x;
    int wid = t >> 5, lane = t & 31;
    int row = blockIdx.x * 8 + wid;
    if (row >= N) return;
    float dv = rsqrtf(g_deg[row]);
    int beg = g_rowstart[row], end = g_rowstart[row + 1];
    float a0 = 0.f, a1 = 0.f, a2 = 0.f;
    for (int k = beg + lane; k < end; k += 32) {
        int2 es = g_es[k];
        int s = es.x;
        float nrm = __int_as_float(es.y);
        a0 = fmaf(nrm, x0[s * 3 + 0], a0);
        a1 = fmaf(nrm, x0[s * 3 + 1], a1);
        a2 = fmaf(nrm, x0[s * 3 + 2], a2);
    }
#pragma unroll
    for (int o = 16; o > 0; o >>= 1) {
        a0 += __shfl_xor_sync(0xffffffff, a0, o);
        a1 += __shfl_xor_sync(0xffffffff, a1, o);
        a2 += __shfl_xor_sync(0xffffffff, a2, o);
    }
    float d2 = dv * dv;
    a0 = fmaf(d2, x0[row * 3 + 0], a0);
    a1 = fmaf(d2, x0[row * 3 + 1], a1);
    a2 = fmaf(d2, x0[row * 3 + 2], a2);
    __half hv[8];
#pragma unroll
    for (int i = 0; i < 8; i++) {
        int c = lane * 8 + i;
        float v = __ldg(&b[c]);
        v = fmaf(a0, __ldg(&W[c]), v);
        v = fmaf(a1, __ldg(&W[256 + c]), v);
        v = fmaf(a2, __ldg(&W[512 + c]), v);
        hv[i] = __float2half_rn(fmaxf(v, 0.0f));
    }
    *(uint4*)&g_x1h[(size_t)row * H + lane * 8] = *(uint4*)hv;
}

// ---------------- layer-2 CSR aggregation: warp per row, fp16 gather/store -----
__device__ __forceinline__ void h8_to_f(const uint4& v, float f[8]) {
    float2 p;
    p = __half22float2(*(const __half2*)&v.x); f[0] = p.x; f[1] = p.y;
    p = __half22float2(*(const __half2*)&v.y); f[2] = p.x; f[3] = p.y;
    p = __half22float2(*(const __half2*)&v.z); f[4] = p.x; f[5] = p.y;
    p = __half22float2(*(const __half2*)&v.w); f[6] = p.x; f[7] = p.y;
}

__global__ __launch_bounds__(256) void k_aggcsr(int N) {
    int wid = threadIdx.x >> 5, lane = threadIdx.x & 31;
    int row = blockIdx.x * 8 + wid;
    if (row >= N) return;
    float dv = rsqrtf(g_deg[row]);
    float d2 = dv * dv;
    float a[8];
    {
        uint4 v = *(const uint4*)&g_x1h[(size_t)row * H + lane * 8];
        float f[8]; h8_to_f(v, f);
#pragma unroll
        for (int i = 0; i < 8; i++) a[i] = d2 * f[i];
    }
    int beg = g_rowstart[row], end = g_rowstart[row + 1];
#pragma unroll 2
    for (int k = beg; k < end; k++) {
        int2 es = g_es[k];
        float nr = __int_as_float(es.y);
        uint4 v = *(const uint4*)&g_x1h[(size_t)es.x * H + lane * 8];
        float f[8]; h8_to_f(v, f);
#pragma unroll
        for (int i = 0; i < 8; i++) a[i] = fmaf(nr, f[i], a[i]);
    }
    __half hv[8];
#pragma unroll
    for (int i = 0; i < 8; i++) hv[i] = __float2half_rn(a[i]);
    *(uint4*)&g_agg[(size_t)row * H + lane * 8] = *(uint4*)hv;
}

// ---------------- mma.sync fp16 GEMM: 128x128 tile, 2-stage pipeline ----------
#define A_OFF 0
#define B_OFF 10240
#define BUF_SZ 18944
#define GEMM_SMEM (2 * BUF_SZ)
#define A_STRIDE 80    // 32 fp16 k-elems (64B) + pad (rows: 128)
#define B_STRIDE 272   // 128 fp16 n-elems (256B) + pad (rows: 32 k)

__device__ __forceinline__ uint32_t smem_u32(const void* p) {
    uint32_t a;
    asm("{ .reg .u64 t; cvta.to.shared.u64 t, %1; cvt.u32.u64 %0, t; }" : "=r"(a) : "l"(p));
    return a;
}
__device__ __forceinline__ void cp16(uint32_t dst, const void* src, int sz) {
    asm volatile("cp.async.cg.shared.global [%0], [%1], 16, %2;" :: "r"(dst), "l"(src), "r"(sz) : "memory");
}
__device__ __forceinline__ void ldsm_x4(uint32_t a[4], uint32_t addr) {
    asm volatile("ldmatrix.sync.aligned.m8n8.x4.shared.b16 {%0,%1,%2,%3}, [%4];"
                 : "=r"(a[0]), "=r"(a[1]), "=r"(a[2]), "=r"(a[3]) : "r"(addr));
}
__device__ __forceinline__ void ldsm_x4t(uint32_t a[4], uint32_t addr) {
    asm volatile("ldmatrix.sync.aligned.m8n8.x4.trans.shared.b16 {%0,%1,%2,%3}, [%4];"
                 : "=r"(a[0]), "=r"(a[1]), "=r"(a[2]), "=r"(a[3]) : "r"(addr));
}
__device__ __forceinline__ void mma_f16(float c[4], const uint32_t a[4], const uint32_t b[2]) {
    asm volatile("mma.sync.aligned.m16n8k16.row.col.f32.f16.f16.f32 "
                 "{%0,%1,%2,%3}, {%4,%5,%6,%7}, {%8,%9}, {%0,%1,%2,%3};"
                 : "+f"(c[0]), "+f"(c[1]), "+f"(c[2]), "+f"(c[3])
                 : "r"(a[0]), "r"(a[1]), "r"(a[2]), "r"(a[3]), "r"(b[0]), "r"(b[1]));
}

__device__ __forceinline__ void prefetch_chunk(
    const __half* __restrict__ A, const __half* __restrict__ B,
    int row0, int col0, int M, int kbase, int tid, uint32_t sbuf) {
#pragma unroll
    for (int l = 0; l < 2; l++) {             // A: 128 rows x 4 vec = 512 vectors
        int idx = tid + l * 256;
        int row = idx >> 2, c4 = idx & 3;
        int gr = row0 + row;
        int sz = (gr < M) ? 16 : 0;
        int grc = (gr < M) ? gr : (M - 1);
        cp16(sbuf + A_OFF + row * A_STRIDE + c4 * 16,
             A + (size_t)grc * H + kbase + c4 * 8, sz);
    }
#pragma unroll
    for (int l = 0; l < 2; l++) {             // B: 32 k x 16 vec = 512 vectors
        int idx = tid + l * 256;
        int kr = idx >> 4, cc = idx & 15;
        cp16(sbuf + B_OFF + kr * B_STRIDE + cc * 16,
             B + (size_t)(kbase + kr) * H + col0 + cc * 8, 16);
    }
    asm volatile("cp.async.commit_group;" ::: "memory");
}

template <int MODE>
__global__ __launch_bounds__(256) void k_mma(const float* __restrict__ bias,
                                             const float* __restrict__ w2,
                                             float* __restrict__ out, int M) {
    extern __shared__ char smem[];
    uint32_t sb = smem_u32(smem);
    int tid = threadIdx.x;
    int lane = tid & 31;
    int wid = tid >> 5;
    int wm = wid & 3, wn = wid >> 2;          // 4 row-groups x 2 col-groups(64)
    int row0 = blockIdx.x * 128;
    int col0 = blockIdx.y * 128;
    const __half* A = (MODE == 0) ? g_agg : g_x2;
    const __half* B = (MODE == 0) ? g_c2 : g_wa;

    float c[2][8][4];
#pragma unroll
    for (int i = 0; i < 2; i++)
#pragma unroll
        for (int j = 0; j < 8; j++)
#pragma unroll
            for (int q = 0; q < 4; q++) c[i][j][q] = 0.f;

    prefetch_chunk(A, B, row0, col0, M, 0, tid, sb + 0);

    for (int ch = 0; ch < 8; ch++) {
        uint32_t buf = sb + (ch & 1) * BUF_SZ;
        asm volatile("cp.async.wait_group 0;" ::: "memory");
        __syncthreads();
        if (ch < 7)
            prefetch_chunk(A, B, row0, col0, M, (ch + 1) * 32, tid, sb + ((ch + 1) & 1) * BUF_SZ);
#pragma unroll
        for (int s = 0; s < 2; s++) {
            uint32_t ah[2][4];
#pragma unroll
            for (int mi = 0; mi < 2; mi++) {
                int r = wm * 32 + mi * 16 + (lane & 15);
                int kb = (s * 16 + (lane >> 4) * 8) * 2;
                ldsm_x4(ah[mi], buf + A_OFF + r * A_STRIDE + kb);
            }
            uint32_t bh[8][2];
#pragma unroll
            for (int ng = 0; ng < 4; ng++) {
                int kr = s * 16 + (lane & 7) + ((lane >> 3) & 1) * 8;
                int nc = wn * 64 + ng * 16 + (lane >> 4) * 8;
                uint32_t t4[4];
                ldsm_x4t(t4, buf + B_OFF + kr * B_STRIDE + nc * 2);
                bh[2 * ng][0] = t4[0]; bh[2 * ng][1] = t4[1];
                bh[2 * ng + 1][0] = t4[2]; bh[2 * ng + 1][1] = t4[3];
            }
#pragma unroll
            for (int mi = 0; mi < 2; mi++)
#pragma unroll
                for (int ni = 0; ni < 8; ni++)
                    mma_f16(c[mi][ni], ah[mi], bh[ni]);
        }
        __syncthreads();
    }

    if (MODE == 0) {
        float* sg = (float*)smem;            // smem free after mainloop
        if (tid < 128) sg[tid] = 0.f;
        __syncthreads();
        float bv[16];
#pragma unroll
        for (int ni = 0; ni < 8; ni++) {
            int col = col0 + wn * 64 + ni * 8 + (lane & 3) * 2;
            bv[ni * 2 + 0] = bias[col];
            bv[ni * 2 + 1] = bias[col + 1];
        }
        float cp[16];
#pragma unroll
        for (int j = 0; j < 16; j++) cp[j] = 0.f;
#pragma unroll
        for (int mi = 0; mi < 2; mi++)
#pragma unroll
            for (int hh = 0; hh < 2; hh++) {
                int row = row0 + wm * 32 + mi * 16 + (lane >> 2) + hh * 8;
                if (row >= M) continue;
#pragma unroll
                for (int ni = 0; ni < 8; ni++) {
                    int col = col0 + wn * 64 + ni * 8 + (lane & 3) * 2;
                    float v0 = fmaxf(c[mi][ni][hh * 2 + 0] + bv[ni * 2 + 0], 0.f);
                    float v1 = fmaxf(c[mi][ni][hh * 2 + 1] + bv[ni * 2 + 1], 0.f);
                    cp[ni * 2 + 0] += v0;
                    cp[ni * 2 + 1] += v1;
                    *(__half2*)&g_x2[(size_t)row * H + col] = __floats2half2_rn(v0, v1);
                }
            }
#pragma unroll
        for (int j = 0; j < 16; j++)
#pragma unroll
            for (int o = 4; o < 32; o <<= 1)
                cp[j] += __shfl_xor_sync(0xffffffff, cp[j], o);
        if ((lane >> 2) == 0) {
#pragma unroll
            for (int ni = 0; ni < 8; ni++) {
                atomicAdd(&sg[wn * 64 + ni * 8 + (lane & 3) * 2 + 0], cp[ni * 2 + 0]);
                atomicAdd(&sg[wn * 64 + ni * 8 + (lane & 3) * 2 + 1], cp[ni * 2 + 1]);
            }
        }
        __syncthreads();
        if (tid < 128) atomicAdd(&g_gsum[col0 + tid], sg[tid]);
    } else {
        float gt[16], wv[16];
#pragma unroll
        for (int ni = 0; ni < 8; ni++) {
            int col = col0 + wn * 64 + ni * 8 + (lane & 3) * 2;
            gt[ni * 2 + 0] = g_gterm[col];
            gt[ni * 2 + 1] = g_gterm[col + 1];
            wv[ni * 2 + 0] = w2[col];
            wv[ni * 2 + 1] = w2[col + 1];
        }
#pragma unroll
        for (int mi = 0; mi < 2; mi++)
#pragma unroll
            for (int hh = 0; hh < 2; hh++) {
                float s = 0.f;
#pragma unroll
                for (int ni = 0; ni < 8; ni++) {
                    float v0 = fmaxf(c[mi][ni][hh * 2 + 0] + gt[ni * 2 + 0], 0.f);
                    float v1 = fmaxf(c[mi][ni][hh * 2 + 1] + gt[ni * 2 + 1], 0.f);
                    s = fmaf(v0, wv[ni * 2 + 0], s);
                    s = fmaf(v1, wv[ni * 2 + 1], s);
                }
                s += __shfl_xor_sync(0xffffffff, s, 1);
                s += __shfl_xor_sync(0xffffffff, s, 2);
                int row = row0 + wm * 32 + mi * 16 + (lane >> 2) + hh * 8;
                if ((lane & 3) == 0 && row < M) atomicAdd(&out[row], s);
            }
    }
}

// ---------------- merged head: gmean -> gterm (actor) + critic value ----------
__global__ void k_head(const float* __restrict__ Wa, const float* __restrict__ ba,
                       const float* __restrict__ W1, const float* __restrict__ b1,
                       const float* __restrict__ W2, const float* __restrict__ b2,
                       const float* __restrict__ w3, const float* __restrict__ b3,
                       float* __restrict__ out, int N) {
    __shared__ float sgm[H];
    __shared__ float sc1[2 * H];
    __shared__ float sred[H];
    int t = threadIdx.x;  // 512
    if (t < H) sgm[t] = g_gsum[t] * (1.0f / (float)N);
    __syncthreads();
    // actor gterm (threads 0..255)
    if (t < H) {
        float acc = ba[t];
        for (int k = 0; k < H; k++) acc = fmaf(sgm[k], Wa[(H + k) * H + t], acc);
        g_gterm[t] = acc;
    }
    // critic layer 1 (all 512 threads)
    float c1 = b1[t];
    for (int k = 0; k < 2 * H; k++) c1 = fmaf(sgm[k & (H - 1)], W1[k * (2 * H) + t], c1);
    sc1[t] = fmaxf(c1, 0.0f);
    __syncthreads();
    if (t < H) {
        float c2 = b2[t];
        for (int k = 0; k < 2 * H; k++) c2 = fmaf(sc1[k], W2[k * H + t], c2);
        sred[t] = fmaxf(c2, 0.0f) * w3[t];
    }
    __syncthreads();
    for (int s = H / 2; s > 0; s >>= 1) {
        if (t < s) sred[t] += sred[t + s];
        __syncthreads();
    }
    if (t == 0) out[N] = sred[0] + b3[0];
}

// ---------------- launch ----------------
extern "C" void kernel_launch(void* const* d_in, const int* in_sizes, int n_in,
                              void* d_out, int out_size) {
    const float* x0       = (const float*)d_in[0];
    const int*   eidx     = (const int*)  d_in[1];
    const int*   eids     = (const int*)  d_in[2];
    const int*   epos     = (const int*)  d_in[3];
    const float* id_emb   = (const float*)d_in[4];
    const float* pos_emb  = (const float*)d_in[5];
    const float* ew_w1    = (const float*)d_in[6];
    const float* ew_b1    = (const float*)d_in[7];
    const float* ew_w2    = (const float*)d_in[8];
    const float* ew_b2    = (const float*)d_in[9];
    const float* conv1_w  = (const float*)d_in[10];
    const float* conv1_b  = (const float*)d_in[11];
    const float* conv2_w  = (const float*)d_in[12];
    const float* conv2_b  = (const float*)d_in[13];
    const float* actor_w1 = (const float*)d_in[14];
    const float* actor_b1 = (const float*)d_in[15];
    const float* actor_w2 = (const float*)d_in[16];
    const float* actor_b2 = (const float*)d_in[17];
    const float* critic_w1= (const float*)d_in[18];
    const float* critic_b1= (const float*)d_in[19];
    const float* critic_w2= (const float*)d_in[20];
    const float* critic_b2= (const float*)d_in[21];
    const float* critic_w3= (const float*)d_in[22];
    const float* critic_b3= (const float*)d_in[23];
    float* out = (float*)d_out;

    int N = in_sizes[0] / 3;
    int E = in_sizes[2];
    const int* src = eidx;
    const int* dst = eidx + E;

    k_prep<<<256, 256>>>(out, actor_b2, conv2_w, actor_w1, N);
    k_edge<<<(E + 255) / 256, 256>>>(eids, epos, id_emb, pos_emb,
                                     ew_w1, ew_b1, ew_w2, ew_b2, dst, E);
    k_scan<<<1, 1024>>>(N, E);
    k_scatter<<<(E + 255) / 256, 256>>>(src, dst, E);
    k_agg0x1<<<(N + 7) / 8, 256>>>(x0, conv1_w, conv1_b, N);
    k_aggcsr<<<(N + 7) / 8, 256>>>(N);

    dim3 gg((N + 127) / 128, 2);
    k_mma<0><<<gg, 256, GEMM_SMEM>>>(conv2_b, nullptr, nullptr, N);
    k_head<<<1, 2 * H>>>(actor_w1, actor_b1, critic_w1, critic_b1,
                         critic_w2, critic_b2, critic_w3, critic_b3, out, N);
    k_mma<1><<<gg, 256, GEMM_SMEM>>>(nullptr, actor_w2, out, N);
}